// round 17
// baseline (speedup 1.0000x reference)
#include <cuda_runtime.h>
#include <cuda_fp16.h>
#include <math.h>

// Problem constants
#define NB 16
#define NO 64
#define NK 63
#define NC 8
#define SEG 128
#define NI 640
#define NAC 24
#define THRv 0.2f
#define TTHR 0.19737532f   // tanh(0.2)

#define NBLK 592
#define NTHR 256
#define NITEM 1042         // 1040 tiles (1024 binary + 16 unary) + biases + DN

// smem (bytes). fp16 rows padded to 136 elems (272B, ldmatrix conflict-free)
#define RPITCH 136
#define S_A 0              // fp16 A: 64 x RPITCH x 2 = 17408
#define S_W 17408          // fp16 W: 48 x RPITCH x 2 = 13056
#define S_TOTAL 30464

// Scratch (device globals; no allocation allowed)
__device__ float g_D[1040 * 64 * 48];   // [tile][row][c]; tiles 1024+b = unary
__device__ float g_DN[NB * NAC];
__device__ float g_andbias[NAC];
__device__ float g_orbias[3];
__device__ float g_nullpart[NB * NO * NC];
__device__ int   g_cnt[NB];             // zero-init; self-resetting
__device__ unsigned g_barcnt;           // zero-init; self-resetting
__device__ unsigned g_gen;              // monotonic across replays

__device__ __forceinline__ float tanhapx(float x) {
    float y; asm("tanh.approx.f32 %0, %1;" : "=f"(y) : "f"(x)); return y;
}
__device__ __forceinline__ unsigned pack_h2(float a, float b) {
    __half2 h = __floats2half2_rn(a, b);
    return *reinterpret_cast<unsigned*>(&h);
}
__device__ __forceinline__ void ldsm_x4(unsigned& r0, unsigned& r1, unsigned& r2, unsigned& r3,
                                        unsigned saddr) {
    asm volatile("ldmatrix.sync.aligned.m8n8.x4.shared.b16 {%0,%1,%2,%3}, [%4];"
                 : "=r"(r0), "=r"(r1), "=r"(r2), "=r"(r3) : "r"(saddr));
}
__device__ __forceinline__ void ldsm_x2(unsigned& r0, unsigned& r1, unsigned saddr) {
    asm volatile("ldmatrix.sync.aligned.m8n8.x2.shared.b16 {%0,%1}, [%2];"
                 : "=r"(r0), "=r"(r1) : "r"(saddr));
}
__device__ __forceinline__ void mma16816(float* d, const unsigned* a, const unsigned* b) {
    asm volatile(
        "mma.sync.aligned.m16n8k16.row.col.f32.f16.f16.f32 "
        "{%0,%1,%2,%3}, {%4,%5,%6,%7}, {%8,%9}, {%0,%1,%2,%3};"
        : "+f"(d[0]), "+f"(d[1]), "+f"(d[2]), "+f"(d[3])
        : "r"(a[0]), "r"(a[1]), "r"(a[2]), "r"(a[3]), "r"(b[0]), "r"(b[1]));
}

// Device-wide barrier: generation-based, replay-safe (g_gen monotonic).
__device__ __forceinline__ void grid_barrier() {
    __syncthreads();
    if (threadIdx.x == 0) {
        __threadfence();
        unsigned gen = *((volatile unsigned*)&g_gen);
        if (atomicAdd(&g_barcnt, 1u) == NBLK - 1) {
            g_barcnt = 0;
            __threadfence();
            atomicAdd(&g_gen, 1u);
        } else {
            while (*((volatile unsigned*)&g_gen) == gen) {}
        }
    }
    __syncthreads();
}

// ---------------------------------------------------------------------------
// One tile: M=64, N=48, K=128, single-pass fp16.
__device__ __forceinline__ void do_tile(int t, char* smx, int& last_wt,
                                        const float* __restrict__ binary,
                                        const float* __restrict__ unary,
                                        const float* __restrict__ andk)
{
    int tid = threadIdx.x;
    bool isU = (t >= 1024);
    int wt = isU ? 1 : 0;

    if (wt != last_wt) {
        int o1 = isU ? 128 : 384;
        int o2 = isU ? 256 : 512;
        #pragma unroll
        for (int it = 0; it < 6; it++) {
            int idx = tid + it * NTHR;      // 0..1535
            int r = idx >> 5, c4 = (idx & 31) * 4;
            int ac = (r < 24) ? r : r - 24;
            int sg = (r < 24) ? o1 : o2;
            float4 v = *(const float4*)(andk + (size_t)ac * NI + sg + c4);
            *(uint2*)(smx + S_W + (unsigned)(r * RPITCH + c4) * 2) =
                make_uint2(pack_h2(v.x, v.y), pack_h2(v.z, v.w));
        }
    }
    last_wt = wt;

    // Stage A (64 rows x 128) as fp16
    #pragma unroll
    for (int it = 0; it < 8; it++) {
        int idx = tid + it * NTHR;          // 0..2047
        int r = idx >> 5, c4 = (idx & 31) * 4;
        float4 v = make_float4(0.f, 0.f, 0.f, 0.f);
        if (isU) {
            v = *(const float4*)(unary + ((size_t)(t - 1024) * NO + r) * SEG + c4);
        } else if (r < NK) {
            v = *(const float4*)(binary + ((size_t)t * NK + r) * SEG + c4);
        }
        *(uint2*)(smx + S_A + (unsigned)(r * RPITCH + c4) * 2) =
            make_uint2(pack_h2(v.x, v.y), pack_h2(v.z, v.w));
    }
    __syncthreads();

    // 8 warps: (mg 0..3) x (ng 0..1). Warp tile m16 x n24.
    int wid = tid >> 5, lane = tid & 31;
    int mg = wid >> 1, ng = wid & 1;
    int c0 = ng * 24;
    float acc[3][4];
    #pragma unroll
    for (int q = 0; q < 3; q++)
        #pragma unroll
        for (int e = 0; e < 4; e++) acc[q][e] = 0.f;

    int aRow = lane & 15, aColH = lane >> 4;
    int bR16 = (lane & 7) + ((lane >> 4) << 3);
    int bC   = (lane >> 3) & 1;

    unsigned ab = (unsigned)__cvta_generic_to_shared(smx + S_A)
                + ((mg * 16 + aRow) * RPITCH + aColH * 8) * 2;
    unsigned w4 = (unsigned)__cvta_generic_to_shared(smx + S_W)
                + ((c0 + bR16) * RPITCH + bC * 8) * 2;
    unsigned w2 = (unsigned)__cvta_generic_to_shared(smx + S_W)
                + ((c0 + 16 + (lane & 7)) * RPITCH + bC * 8) * 2;

    #pragma unroll
    for (int k0 = 0; k0 < 8; k0++) {
        unsigned koff = k0 * 32;
        unsigned a[4], b[6];
        ldsm_x4(a[0], a[1], a[2], a[3], ab + koff);
        ldsm_x4(b[0], b[1], b[2], b[3], w4 + koff);
        ldsm_x2(b[4], b[5], w2 + koff);
        mma16816(acc[0], a, &b[0]);
        mma16816(acc[1], a, &b[2]);
        mma16816(acc[2], a, &b[4]);
    }

    size_t tbase = (size_t)t * 64 * 48;
    int rr = mg * 16 + (lane >> 2);
    #pragma unroll
    for (int q = 0; q < 3; q++) {
        int cc = c0 + q * 8 + (lane & 3) * 2;
        *(float2*)&g_D[tbase + (size_t)rr * 48 + cc]       = make_float2(acc[q][0], acc[q][1]);
        *(float2*)&g_D[tbase + (size_t)(rr + 8) * 48 + cc] = make_float2(acc[q][2], acc[q][3]);
    }
    __syncthreads();   // smem safe to restage
}

// ---------------------------------------------------------------------------
__global__ __launch_bounds__(NTHR, 6) void fused_kernel(
    const float* __restrict__ nullary,
    const float* __restrict__ unary,
    const float* __restrict__ binary,
    const float* __restrict__ andk,
    const float* __restrict__ ork,
    float* __restrict__ out)
{
    extern __shared__ char smx[];
    int bid = blockIdx.x;
    int tid = threadIdx.x;

    // ---- Phase 1: work items bid, bid+592 ----
    int last_wt = -1;
    for (int item = bid; item < NITEM; item += NBLK) {
        if (item < 1040) {
            do_tile(item, smx, last_wt, binary, unary, andk);
        } else if (item == 1040) {
            float* sred = (float*)smx;  // 24 x 8 partials
            if (tid < 192) {
                int row = tid >> 3, part = tid & 7;
                const float* w = andk + (size_t)row * NI + part * 80;
                float s = 0.f;
                #pragma unroll 8
                for (int k = 0; k < 80; k++) { float v = w[k]; s += v * v; }
                sred[row * 8 + part] = s;
            }
            __syncthreads();
            if (tid < NAC) {
                float s = 0.f;
                #pragma unroll
                for (int p = 0; p < 8; p++) s += sred[tid * 8 + p];
                g_andbias[tid] = THRv - s * TTHR;
            } else if (tid < 27) {
                int a = tid - NAC;
                float s = 0.f;
                #pragma unroll
                for (int c = 0; c < NC; c++) { float v = ork[a * NC + c]; s += v * v; }
                g_orbias[a] = s * TTHR - THRv;
            }
            __syncthreads();
        } else {
            for (int d = tid; d < NB * NAC; d += NTHR) {
                int b = d / NAC, ac = d % NAC;
                const float* w = andk + (size_t)ac * NI;
                const float* nv = nullary + b * SEG;
                float s = 0.f;
                #pragma unroll 8
                for (int k = 0; k < SEG; k++) s += nv[k] * w[k];
                g_DN[d] = s;
            }
            __syncthreads();
        }
    }

    // ---- Global barrier ----
    grid_barrier();

    // ---- Phase 2: combine (blocks 0..511, 2 gi each) ----
    if (bid < 512) {
        float* base   = (float*)smx;              // 2 x 24
        float* red    = (float*)(smx + 512);      // 2 x 64 x 17
        float* colmax = (float*)(smx + 9216);     // 2 x 16
        int*   isLast = (int*)(smx + 9344);

        int tile = tid >> 7;          // 0..1
        int t2   = tid & 127;
        int k    = t2 & 63;
        int half = t2 >> 6;
        int gi = bid * 2 + tile;
        int b = bid >> 5;             // uniform per block
        int i = gi & 63;

        if (tid < 48) {
            int tt = tid / NAC, c = tid % NAC;
            int i2 = (bid * 2 + tt) & 63;
            base[tt * NAC + c] = g_andbias[c] + g_DN[b * NAC + c]
                               + g_D[((size_t)(1024 + b) * 64 + i2) * 48 + c];
        }
        __syncthreads();

        bool act = (k < NK);
        int j  = k + (k >= i ? 1 : 0);
        int ip = (k < i) ? (i - 1) : i;
        const float4* du1 = (const float4*)(g_D + ((size_t)(1024 + b) * 64 + j) * 48 + 24 + half * 12);
        const float4* db0 = (const float4*)(g_D + ((size_t)gi * 64 + k) * 48 + half * 12);
        const float4* db1 = (const float4*)(g_D + ((size_t)(b * 64 + j) * 64 + ip) * 48 + 24 + half * 12);

        float s[12];
        if (act) {
            #pragma unroll
            for (int q = 0; q < 3; q++) {
                float4 u  = __ldg(du1 + q);
                float4 v0 = __ldg(db0 + q);
                float4 v1 = __ldg(db1 + q);
                int cb = half * 12 + 4 * q;
                s[4 * q + 0] = base[tile * NAC + cb + 0] + u.x + v0.x + v1.x;
                s[4 * q + 1] = base[tile * NAC + cb + 1] + u.y + v0.y + v1.y;
                s[4 * q + 2] = base[tile * NAC + cb + 2] + u.z + v0.z + v1.z;
                s[4 * q + 3] = base[tile * NAC + cb + 3] + u.w + v0.w + v1.w;
            }
        }

        float* redr = red + (tile * 64 + k) * 17;
        if (half == 0) {
            #pragma unroll
            for (int c = 0; c < 12; c++)
                redr[c] = act ? tanhapx(s[c]) : -2.0f;
        } else {
            #pragma unroll
            for (int c = 0; c < 4; c++)
                redr[12 + c] = act ? tanhapx(s[c]) : -2.0f;
            if (act) {
                float s2 = g_orbias[2];
                #pragma unroll
                for (int c = 0; c < NC; c++) s2 += tanhapx(s[4 + c]) * __ldg(ork + 16 + c);
                out[16 + NB * NO + (size_t)gi * NK + k] = s2;
            }
        }
        __syncthreads();

        if (tid < 32) {
            int tt = tid >> 4, cc = tid & 15;
            float m = red[(tt * 64 + 0) * 17 + cc];
            #pragma unroll 8
            for (int r = 1; r < 64; r++) m = fmaxf(m, red[(tt * 64 + r) * 17 + cc]);
            colmax[tt * 16 + cc] = m;
        }
        __syncthreads();
        if (t2 == 0) {
            float s1 = g_orbias[1];
            #pragma unroll
            for (int c = 0; c < NC; c++) s1 += colmax[tile * 16 + 8 + c] * __ldg(ork + 8 + c);
            out[16 + gi] = s1;
        }
        if (t2 < NC) g_nullpart[gi * NC + t2] = colmax[tile * 16 + t2];

        // Fused final-null reduce: last of the 32 blocks for this b.
        __syncthreads();
        if (tid == 0) {
            __threadfence();
            int v = atomicAdd(&g_cnt[b], 1);
            *isLast = (v == 31) ? 1 : 0;
        }
        __syncthreads();
        if (*isLast) {
            __threadfence();
            if (tid < NC) {
                float m = -2.0f;
                #pragma unroll 8
                for (int r = 0; r < NO; r++)
                    m = fmaxf(m, g_nullpart[(b * NO + r) * NC + tid]);
                colmax[tid] = m;
            }
            __syncthreads();
            if (tid == 0) {
                float s0 = g_orbias[0];
                #pragma unroll
                for (int c = 0; c < NC; c++) s0 += colmax[c] * __ldg(ork + c);
                out[b] = s0;
                g_cnt[b] = 0;   // reset for next graph replay
            }
        }
    }
}

// ---------------------------------------------------------------------------
extern "C" void kernel_launch(void* const* d_in, const int* in_sizes, int n_in,
                              void* d_out, int out_size)
{
    const float* nullary = (const float*)d_in[0];
    const float* unary   = (const float*)d_in[1];
    const float* binary  = (const float*)d_in[2];
    const float* andk    = (const float*)d_in[3];
    const float* ork     = (const float*)d_in[4];
    float* out = (float*)d_out;

    cudaFuncSetAttribute(fused_kernel, cudaFuncAttributeMaxDynamicSharedMemorySize, S_TOTAL);
    fused_kernel<<<NBLK, NTHR, S_TOTAL>>>(nullary, unary, binary, andk, ork, out);
}